// round 1
// baseline (speedup 1.0000x reference)
#include <cuda_runtime.h>
#include <stdint.h>

#define Bn 16384
#define Tn 256
#define Dn 8
#define Fn 512
#define Cn 16
#define Ln 256

#define TTILES 16            // tree tiles (16 trees each)
#define BTILES 16            // sample tiles (1024 samples each)
#define BTILE  1024

// ---------------- device scratch (static, no runtime allocation) ------------
__device__ unsigned short g_fidx16[Tn * Dn];                 // 4 KB
__device__ unsigned char  g_dec[(size_t)Tn * Bn];            // 4 MB, layout [T][B]
__device__ float          g_part[(size_t)TTILES * Bn * Cn];  // 16 MB partial sums

// ---------------- kernel 1: argmax over F per (tree, depth) -----------------
// one warp per (t,d); first-occurrence tiebreak to match jnp.argmax
__global__ void k_argmax(const float* __restrict__ fw) {
    int g    = blockIdx.x * 8 + (threadIdx.x >> 5);   // 2048 warps total
    int lane = threadIdx.x & 31;
    const float* p = fw + (size_t)g * Fn;

    float best = -__int_as_float(0x7f800000);  // -inf
    int   bi   = lane;                          // first candidate index
    bool  init = false;
    #pragma unroll
    for (int i = 0; i < Fn / 32; i++) {
        int   f = lane + (i << 5);
        float v = p[f];
        if (!init || v > best) { best = v; bi = f; init = true; }
    }
    #pragma unroll
    for (int off = 16; off; off >>= 1) {
        float ov = __shfl_down_sync(0xffffffffu, best, off);
        int   oi = __shfl_down_sync(0xffffffffu, bi,   off);
        if (ov > best || (ov == best && oi < bi)) { best = ov; bi = oi; }
    }
    if (lane == 0) g_fidx16[g] = (unsigned short)bi;
}

// ---------------- kernel 2: per-(sample,tree) decision byte -----------------
// block = 32 samples, 256 threads = 8 warps, each warp owns 32 trees.
// x rows in smem with stride 513 floats -> gather bank = (lane + f) % 32,
// conflict-free. Output written tree-major: g_dec[t*Bn + b] (coalesced 32B).
__global__ void k_decide(const float* __restrict__ x,
                         const float* __restrict__ thr) {
    extern __shared__ float smem[];
    float* s_x   = smem;                                   // 32 * 513 floats
    uint4* s_fpk = (uint4*)(smem + 32 * 513);              // 256 * 16 B
    float* s_thr = (float*)(s_fpk + Tn);                   // 2048 floats

    int tid = threadIdx.x;
    int b0  = blockIdx.x * 32;

    // stage 32 x-rows (float4 global loads, scalar smem stores due to padding)
    const float4* xg = (const float4*)x + (size_t)b0 * (Fn / 4);
    for (int i = tid; i < 32 * (Fn / 4); i += 256) {
        float4 v = xg[i];
        int row = i >> 7, c4 = i & 127;
        float* dst = s_x + row * 513 + c4 * 4;
        dst[0] = v.x; dst[1] = v.y; dst[2] = v.z; dst[3] = v.w;
    }
    // stage packed feature indices (2048 u16 = 1024 u32) and thresholds
    for (int i = tid; i < (Tn * Dn) / 2; i += 256)
        ((unsigned*)s_fpk)[i] = ((const unsigned*)g_fidx16)[i];
    for (int i = tid; i < Tn * Dn; i += 256)
        s_thr[i] = thr[i];
    __syncthreads();

    int warp = tid >> 5, lane = tid & 31;
    const float* xr = s_x + lane * 513;   // this lane's sample row

    #pragma unroll 4
    for (int tt = 0; tt < 32; tt++) {
        int t = warp * 32 + tt;
        uint4 fp = s_fpk[t];
        const float4* th = (const float4*)(s_thr + t * 8);
        float4 t0 = th[0], t1 = th[1];
        unsigned dec = 0;
        dec = (dec << 1) | (unsigned)(xr[fp.x & 0xFFFFu] > t0.x);
        dec = (dec << 1) | (unsigned)(xr[fp.x >> 16]     > t0.y);
        dec = (dec << 1) | (unsigned)(xr[fp.y & 0xFFFFu] > t0.z);
        dec = (dec << 1) | (unsigned)(xr[fp.y >> 16]     > t0.w);
        dec = (dec << 1) | (unsigned)(xr[fp.z & 0xFFFFu] > t1.x);
        dec = (dec << 1) | (unsigned)(xr[fp.z >> 16]     > t1.y);
        dec = (dec << 1) | (unsigned)(xr[fp.w & 0xFFFFu] > t1.z);
        dec = (dec << 1) | (unsigned)(xr[fp.w >> 16]     > t1.w);
        g_dec[(size_t)t * Bn + b0 + lane] = (unsigned char)dec;
    }
}

// ---------------- kernel 3: leaf gather + per-tree-tile accumulation --------
// grid (BTILES, TTILES). Block = 512 threads, 1024 samples, 16 trees.
// responses[t] staged in smem with rows padded to 32 words and float4 slots
// swizzled by (k + 5d) & 7 -> random-decision LDS.128 gathers hit the
// 4-phase floor instead of 16-way bank clustering.
__global__ __launch_bounds__(512) void k_accum(const float* __restrict__ resp) {
    __shared__ float4   s_r[Ln * 8];     // 32 KB (8 float4 slots per leaf row)
    __shared__ unsigned s_du[BTILE / 4]; // 1 KB of decision bytes

    int tid   = threadIdx.x;
    int b0    = blockIdx.x * BTILE;
    int tbase = blockIdx.y * (Tn / TTILES);

    float4 a[8];
    #pragma unroll
    for (int k = 0; k < 8; k++) a[k] = make_float4(0.f, 0.f, 0.f, 0.f);

    for (int tt = 0; tt < Tn / TTILES; tt++) {
        int t = tbase + tt;
        __syncthreads();
        const float4* rs = (const float4*)resp + (size_t)t * (Ln * Cn / 4);
        #pragma unroll
        for (int i = tid; i < Ln * Cn / 4; i += 512) {   // 1024 float4
            float4 v = rs[i];
            int d = i >> 2, k = i & 3;
            s_r[d * 8 + ((k + 5 * d) & 7)] = v;
        }
        if (tid < BTILE / 4)
            s_du[tid] = ((const unsigned*)(g_dec + (size_t)t * Bn + b0))[tid];
        __syncthreads();

        const unsigned char* sd = (const unsigned char*)s_du;
        int d0 = sd[tid];
        int d1 = sd[tid + 512];
        const float4* r0 = s_r + d0 * 8; int o0 = (5 * d0) & 7;
        const float4* r1 = s_r + d1 * 8; int o1 = (5 * d1) & 7;
        #pragma unroll
        for (int k = 0; k < 4; k++) {
            float4 v0 = r0[(k + o0) & 7];
            a[k].x += v0.x; a[k].y += v0.y; a[k].z += v0.z; a[k].w += v0.w;
            float4 v1 = r1[(k + o1) & 7];
            a[4 + k].x += v1.x; a[4 + k].y += v1.y;
            a[4 + k].z += v1.z; a[4 + k].w += v1.w;
        }
    }

    // write partial sums for this tree tile (deterministic; no atomics)
    float4* p0 = (float4*)(g_part + ((size_t)blockIdx.y * Bn + b0 + tid) * Cn);
    float4* p1 = (float4*)(g_part + ((size_t)blockIdx.y * Bn + b0 + 512 + tid) * Cn);
    #pragma unroll
    for (int k = 0; k < 4; k++) { p0[k] = a[k]; p1[k] = a[4 + k]; }
}

// ---------------- kernel 4: reduce partials across tree tiles ---------------
__global__ void k_reduce(float* __restrict__ out) {
    int i = blockIdx.x * blockDim.x + threadIdx.x;     // float4 index, 65536
    const float4* p = (const float4*)g_part;
    float4 s = make_float4(0.f, 0.f, 0.f, 0.f);
    #pragma unroll
    for (int tt = 0; tt < TTILES; tt++) {
        float4 v = p[(size_t)tt * (Bn * Cn / 4) + i];
        s.x += v.x; s.y += v.y; s.z += v.z; s.w += v.w;
    }
    const float sc = 1.0f / (float)Tn;
    s.x *= sc; s.y *= sc; s.z *= sc; s.w *= sc;
    ((float4*)out)[i] = s;
}

// ---------------- launch ------------------------------------------------------
extern "C" void kernel_launch(void* const* d_in, const int* in_sizes, int n_in,
                              void* d_out, int out_size) {
    const float* x    = (const float*)d_in[0];   // (B, F)
    const float* fw   = (const float*)d_in[1];   // (T, D, F)
    const float* thr  = (const float*)d_in[2];   // (T, D)
    const float* resp = (const float*)d_in[3];   // (T, L, C)
    float* out = (float*)d_out;                  // (B, C)

    const int smem2 = 32 * 513 * 4 + Tn * 16 + Tn * Dn * 4;  // 77952 B
    static int attr_done = 0;
    // idempotent attribute set (host-side config, not a stream op; not captured)
    cudaFuncSetAttribute(k_decide, cudaFuncAttributeMaxDynamicSharedMemorySize,
                         smem2);
    (void)attr_done; (void)in_sizes; (void)n_in; (void)out_size;

    k_argmax<<<(Tn * Dn) / 8, 256>>>(fw);
    k_decide<<<Bn / 32, 256, smem2>>>(x, thr);
    k_accum<<<dim3(BTILES, TTILES), 512>>>(resp);
    k_reduce<<<(Bn * Cn / 4) / 512, 512>>>(out);
}

// round 2
// speedup vs baseline: 1.0959x; 1.0959x over previous
#include <cuda_runtime.h>
#include <stdint.h>

#define Bn 16384
#define Tn 256
#define Dn 8
#define Fn 512
#define Cn 16
#define Ln 256

#define TTILES 16            // tree tiles (16 trees each)
#define BTILES 16            // sample tiles (1024 samples each)
#define BTILE  1024

// ---------------- device scratch (static, no runtime allocation) ------------
__device__ unsigned short g_fidx16[Tn * Dn];                 // 4 KB
__device__ unsigned char  g_dec[(size_t)Tn * Bn];            // 4 MB, layout [T][B]
__device__ float          g_part[(size_t)TTILES * Bn * Cn];  // 16 MB partial sums

// ---------------- kernel 1: argmax over F per (tree, depth) -----------------
__global__ void k_argmax(const float* __restrict__ fw) {
    int g    = blockIdx.x * 8 + (threadIdx.x >> 5);   // 2048 warps total
    int lane = threadIdx.x & 31;
    const float* p = fw + (size_t)g * Fn;

    float best = -__int_as_float(0x7f800000);
    int   bi   = lane;
    bool  init = false;
    #pragma unroll
    for (int i = 0; i < Fn / 32; i++) {
        int   f = lane + (i << 5);
        float v = p[f];
        if (!init || v > best) { best = v; bi = f; init = true; }
    }
    #pragma unroll
    for (int off = 16; off; off >>= 1) {
        float ov = __shfl_down_sync(0xffffffffu, best, off);
        int   oi = __shfl_down_sync(0xffffffffu, bi,   off);
        if (ov > best || (ov == best && oi < bi)) { best = ov; bi = oi; }
    }
    if (lane == 0) g_fidx16[g] = (unsigned short)bi;
}

// ---------------- kernel 2: per-(sample,tree) decision byte -----------------
// block = 32 samples, 512 threads = 16 warps, each warp owns 16 trees.
// x rows in smem with stride 513 floats -> gather bank = (lane + f) % 32,
// conflict-free. Output tree-major: g_dec[t*Bn + b] (coalesced 32B).
__global__ __launch_bounds__(512) void k_decide(const float* __restrict__ x,
                                                const float* __restrict__ thr) {
    extern __shared__ float smem[];
    float* s_x   = smem;                                   // 32 * 513 floats
    uint4* s_fpk = (uint4*)(smem + 32 * 513);              // 256 * 16 B
    float* s_thr = (float*)(s_fpk + Tn);                   // 2048 floats

    int tid = threadIdx.x;
    int b0  = blockIdx.x * 32;

    const float4* xg = (const float4*)x + (size_t)b0 * (Fn / 4);
    for (int i = tid; i < 32 * (Fn / 4); i += 512) {
        float4 v = xg[i];
        int row = i >> 7, c4 = i & 127;
        float* dst = s_x + row * 513 + c4 * 4;
        dst[0] = v.x; dst[1] = v.y; dst[2] = v.z; dst[3] = v.w;
    }
    for (int i = tid; i < (Tn * Dn) / 2; i += 512)
        ((unsigned*)s_fpk)[i] = ((const unsigned*)g_fidx16)[i];
    for (int i = tid; i < Tn * Dn; i += 512)
        s_thr[i] = thr[i];
    __syncthreads();

    int warp = tid >> 5, lane = tid & 31;
    const float* xr = s_x + lane * 513;

    #pragma unroll 4
    for (int tt = 0; tt < 16; tt++) {
        int t = warp * 16 + tt;
        uint4 fp = s_fpk[t];
        const float4* th = (const float4*)(s_thr + t * 8);
        float4 t0 = th[0], t1 = th[1];
        unsigned dec = 0;
        dec = (dec << 1) | (unsigned)(xr[fp.x & 0xFFFFu] > t0.x);
        dec = (dec << 1) | (unsigned)(xr[fp.x >> 16]     > t0.y);
        dec = (dec << 1) | (unsigned)(xr[fp.y & 0xFFFFu] > t0.z);
        dec = (dec << 1) | (unsigned)(xr[fp.y >> 16]     > t0.w);
        dec = (dec << 1) | (unsigned)(xr[fp.z & 0xFFFFu] > t1.x);
        dec = (dec << 1) | (unsigned)(xr[fp.z >> 16]     > t1.y);
        dec = (dec << 1) | (unsigned)(xr[fp.w & 0xFFFFu] > t1.z);
        dec = (dec << 1) | (unsigned)(xr[fp.w >> 16]     > t1.w);
        g_dec[(size_t)t * Bn + b0 + lane] = (unsigned char)dec;
    }
}

// ---------------- kernel 3: leaf gather, double-buffered staging ------------
// grid (BTILES, TTILES). Block = 512 threads, 1024 samples, 16 trees.
// responses[t] staged into alternating smem buffers; LDG for tree tt+1 issued
// before the gather of tree tt so staging latency is hidden. Rows padded to
// 8 float4 slots with (k + 5d) & 7 swizzle for near-floor LDS.128 gathers.
__global__ __launch_bounds__(512) void k_accum(const float* __restrict__ resp) {
    extern __shared__ float4 dynsmem[];
    float4*   s_r  = dynsmem;                         // 2 * Ln*8 float4 = 64 KB
    unsigned* s_du = (unsigned*)(dynsmem + 2 * Ln * 8);  // 2 * 256 u32 = 2 KB

    int tid   = threadIdx.x;
    int b0    = blockIdx.x * BTILE;
    int tbase = blockIdx.y * (Tn / TTILES);

    float4 a[8];
    #pragma unroll
    for (int k = 0; k < 8; k++) a[k] = make_float4(0.f, 0.f, 0.f, 0.f);

    // prologue: stage tree tbase into buffer 0
    {
        const float4* rs = (const float4*)resp + (size_t)tbase * (Ln * Cn / 4);
        #pragma unroll
        for (int j = 0; j < 2; j++) {
            int i = tid + j * 512;
            float4 v = rs[i];
            int d = i >> 2, k = i & 3;
            s_r[d * 8 + ((k + 5 * d) & 7)] = v;
        }
        if (tid < BTILE / 4)
            s_du[tid] = ((const unsigned*)(g_dec + (size_t)tbase * Bn + b0))[tid];
    }
    __syncthreads();

    for (int tt = 0; tt < Tn / TTILES; tt++) {
        int cur = tt & 1;
        // issue next tree's global loads early (latency hidden by gather below)
        float4 nv0, nv1; unsigned ndu = 0;
        bool have = (tt + 1 < Tn / TTILES);
        if (have) {
            int t = tbase + tt + 1;
            const float4* rs = (const float4*)resp + (size_t)t * (Ln * Cn / 4);
            nv0 = rs[tid];
            nv1 = rs[tid + 512];
            if (tid < BTILE / 4)
                ndu = ((const unsigned*)(g_dec + (size_t)t * Bn + b0))[tid];
        }

        const unsigned char* sd = (const unsigned char*)(s_du + cur * (BTILE / 4));
        const float4* sr = s_r + cur * (Ln * 8);
        int d0 = sd[tid];
        int d1 = sd[tid + 512];
        const float4* r0 = sr + d0 * 8; int o0 = (5 * d0) & 7;
        const float4* r1 = sr + d1 * 8; int o1 = (5 * d1) & 7;
        #pragma unroll
        for (int k = 0; k < 4; k++) {
            float4 v0 = r0[(k + o0) & 7];
            a[k].x += v0.x; a[k].y += v0.y; a[k].z += v0.z; a[k].w += v0.w;
            float4 v1 = r1[(k + o1) & 7];
            a[4 + k].x += v1.x; a[4 + k].y += v1.y;
            a[4 + k].z += v1.z; a[4 + k].w += v1.w;
        }

        if (have) {
            int nb = cur ^ 1;
            float4* dr = s_r + nb * (Ln * 8);
            { int i = tid;       int d = i >> 2, k = i & 3; dr[d * 8 + ((k + 5 * d) & 7)] = nv0; }
            { int i = tid + 512; int d = i >> 2, k = i & 3; dr[d * 8 + ((k + 5 * d) & 7)] = nv1; }
            if (tid < BTILE / 4) s_du[nb * (BTILE / 4) + tid] = ndu;
        }
        __syncthreads();
    }

    float4* p0 = (float4*)(g_part + ((size_t)blockIdx.y * Bn + b0 + tid) * Cn);
    float4* p1 = (float4*)(g_part + ((size_t)blockIdx.y * Bn + b0 + 512 + tid) * Cn);
    #pragma unroll
    for (int k = 0; k < 4; k++) { p0[k] = a[k]; p1[k] = a[4 + k]; }
}

// ---------------- kernel 4: reduce partials across tree tiles ---------------
// scalar lanes: 262144 threads, 16 independent loads each (high MLP)
__global__ void k_reduce(float* __restrict__ out) {
    int i = blockIdx.x * 256 + threadIdx.x;       // 0 .. Bn*Cn-1
    float s = 0.f;
    #pragma unroll
    for (int tt = 0; tt < TTILES; tt++)
        s += g_part[(size_t)tt * (Bn * Cn) + i];
    out[i] = s * (1.0f / (float)Tn);
}

// ---------------- launch -----------------------------------------------------
extern "C" void kernel_launch(void* const* d_in, const int* in_sizes, int n_in,
                              void* d_out, int out_size) {
    const float* x    = (const float*)d_in[0];   // (B, F)
    const float* fw   = (const float*)d_in[1];   // (T, D, F)
    const float* thr  = (const float*)d_in[2];   // (T, D)
    const float* resp = (const float*)d_in[3];   // (T, L, C)
    float* out = (float*)d_out;                  // (B, C)

    const int smem_dec = 32 * 513 * 4 + Tn * 16 + Tn * Dn * 4;        // 77952 B
    const int smem_acc = 2 * Ln * 8 * 16 + 2 * (BTILE / 4) * 4;       // 67584 B
    cudaFuncSetAttribute(k_decide, cudaFuncAttributeMaxDynamicSharedMemorySize,
                         smem_dec);
    cudaFuncSetAttribute(k_accum, cudaFuncAttributeMaxDynamicSharedMemorySize,
                         smem_acc);
    (void)in_sizes; (void)n_in; (void)out_size;

    k_argmax<<<(Tn * Dn) / 8, 256>>>(fw);
    k_decide<<<Bn / 32, 512, smem_dec>>>(x, thr);
    k_accum<<<dim3(BTILES, TTILES), 512, smem_acc>>>(resp);
    k_reduce<<<(Bn * Cn) / 256, 256>>>(out);
}